// round 8
// baseline (speedup 1.0000x reference)
#include <cuda_runtime.h>
#include <math.h>

#define NNODE 4096
#define DIM   200
#define TT    4
#define HEADS 8
#define GDIM  (DIM*DIM)          // 40000
#define MBATCH (TT*NNODE)        // 16384
#define WVSZ  (HEADS*DIM*DIM)    // 320000
#define WCATC 600                // 3*DIM

// ---------------- scratch (device globals; no allocation allowed) ----------------
__device__ float g_W2eff[GDIM];
__device__ float g_Wcat[NNODE*WCATC];
__device__ float g_Ucat[DIM*2*DIM];
__device__ float g_H[MBATCH*DIM];
__device__ float g_O[MBATCH*DIM];
__device__ float g_S[NNODE*WCATC];
__device__ float g_G[3*GDIM];
__device__ float g_Gpart[24*GDIM];
__device__ float g_wv[WVSZ];
__device__ float g_A12[HEADS*DIM*2*DIM];
__device__ float g_A3[WVSZ];
__device__ float g_rw[WVSZ];
__device__ float g_ub[WVSZ];

// ---------------- small helpers ----------------
__global__ void copyk(float* __restrict__ dst, const float* __restrict__ src, int n) {
    int i = blockIdx.x * blockDim.x + threadIdx.x;
    if (i < n) dst[i] = src[i];
}

__global__ void build_w2eff(const float* __restrict__ W2, float* __restrict__ out) {
    int idx = blockIdx.x * blockDim.x + threadIdx.x;
    if (idx >= GDIM) return;
    int o = idx / DIM, j = idx % DIM;
    float s = 0.f;
#pragma unroll
    for (int k = 0; k < HEADS; k++) s += W2[(size_t)o * (HEADS*DIM) + k*DIM + j];
    out[idx] = s;
}

__global__ void build_wcat(const float* __restrict__ Wr, const float* __restrict__ Wu,
                           const float* __restrict__ Wh, float* __restrict__ out) {
    int idx = blockIdx.x * blockDim.x + threadIdx.x;
    if (idx >= NNODE*DIM) return;
    int k = idx / DIM, j = idx % DIM;
    out[(size_t)k*WCATC + j]        = Wr[idx];
    out[(size_t)k*WCATC + DIM + j]  = Wu[idx];
    out[(size_t)k*WCATC + 2*DIM + j]= Wh[idx];
}

__global__ void build_ucat(const float* __restrict__ Ur, const float* __restrict__ Uu,
                           float* __restrict__ out) {
    int idx = blockIdx.x * blockDim.x + threadIdx.x;
    if (idx >= GDIM) return;
    int k = idx / DIM, j = idx % DIM;
    out[(size_t)k*(2*DIM) + j]       = Ur[idx];
    out[(size_t)k*(2*DIM) + DIM + j] = Uu[idx];
}

// ---------------- generic tiled SGEMM: C = A @ op(B) (+bias, elu) ----------------
// 64x64 tile, BK=16, 256 threads, 4x4 micro-tile.
// TRANSB: B stored [N,K] (ldb = row stride), op(B)=B^T. else B stored [K,N].
template<bool TRANSB, bool BIAS_ELU>
__global__ void sgemm64(const float* __restrict__ A, int lda,
                        const float* __restrict__ B, int ldb,
                        const float* __restrict__ bias,
                        float* __restrict__ C, int ldc,
                        int M, int N, int K)
{
    __shared__ float As[16][64];
    __shared__ float Bs[16][64];
    const int tid = threadIdx.x;
    const int tx = tid & 15, ty = tid >> 4;
    const int row0 = blockIdx.y * 64, col0 = blockIdx.x * 64;
    float acc[4][4];
#pragma unroll
    for (int i = 0; i < 4; i++)
#pragma unroll
        for (int j = 0; j < 4; j++) acc[i][j] = 0.f;

    const int ar = tid >> 2;          // 0..63
    const int ak = (tid & 3) * 4;     // 0,4,8,12

    for (int k0 = 0; k0 < K; k0 += 16) {
        // A tile -> As[k][row]
        {
            float v[4] = {0.f,0.f,0.f,0.f};
            int arow = row0 + ar;
            if (arow < M) {
                const float* ap = A + (size_t)arow * lda + k0 + ak;
#pragma unroll
                for (int q = 0; q < 4; q++) { if (k0 + ak + q < K) v[q] = ap[q]; }
            }
#pragma unroll
            for (int q = 0; q < 4; q++) As[ak + q][ar] = v[q];
        }
        // B tile -> Bs[k][col]
        if (!TRANSB) {
            int bk = tid >> 4;          // 0..15
            int bc = (tid & 15) * 4;    // 0..60
            float v[4] = {0.f,0.f,0.f,0.f};
            if (k0 + bk < K) {
                const float* bp = B + (size_t)(k0 + bk) * ldb + col0 + bc;
#pragma unroll
                for (int q = 0; q < 4; q++) { if (col0 + bc + q < N) v[q] = bp[q]; }
            }
#pragma unroll
            for (int q = 0; q < 4; q++) Bs[bk][bc + q] = v[q];
        } else {
            int bn = tid >> 2;          // 0..63 (output col)
            int bk = (tid & 3) * 4;
            float v[4] = {0.f,0.f,0.f,0.f};
            if (col0 + bn < N) {
                const float* bp = B + (size_t)(col0 + bn) * ldb + k0 + bk;
#pragma unroll
                for (int q = 0; q < 4; q++) { if (k0 + bk + q < K) v[q] = bp[q]; }
            }
#pragma unroll
            for (int q = 0; q < 4; q++) Bs[bk + q][bn] = v[q];
        }
        __syncthreads();
#pragma unroll
        for (int kk = 0; kk < 16; kk++) {
            float a[4], b[4];
#pragma unroll
            for (int i = 0; i < 4; i++) a[i] = As[kk][ty*4 + i];
#pragma unroll
            for (int j = 0; j < 4; j++) b[j] = Bs[kk][tx*4 + j];
#pragma unroll
            for (int i = 0; i < 4; i++)
#pragma unroll
                for (int j = 0; j < 4; j++) acc[i][j] += a[i] * b[j];
        }
        __syncthreads();
    }

#pragma unroll
    for (int i = 0; i < 4; i++) {
        int row = row0 + ty*4 + i;
        if (row >= M) continue;
#pragma unroll
        for (int j = 0; j < 4; j++) {
            int col = col0 + tx*4 + j;
            if (col >= N) continue;
            float v = acc[i][j];
            if (BIAS_ELU) { v += bias[col]; v = v > 0.f ? v : expm1f(v); }
            C[(size_t)row * ldc + col] = v;
        }
    }
}

// ---------------- split-K batched GEMM for G_g = P_g @ S[:, g*200:(g+1)*200] ----
// grid (4, 4, 24): z -> gate g = z>>3, k-chunk s = z&7 (K chunks of 512).
// Writes deterministic partials; reduce_g sums them in fixed order.
__global__ void sgemm_ps(const float* __restrict__ Pr, const float* __restrict__ Pu,
                         const float* __restrict__ Ph, const float* __restrict__ S,
                         float* __restrict__ Gpart)
{
    __shared__ float As[16][64];
    __shared__ float Bs[16][64];
    const int z = blockIdx.z, g = z >> 3, s = z & 7;
    const float* A = (g == 0) ? Pr : ((g == 1) ? Pu : Ph);   // [200, 4096]
    const float* B = S + g * DIM;                            // ldb = 600
    float* C = Gpart + (size_t)z * GDIM;

    const int tid = threadIdx.x;
    const int tx = tid & 15, ty = tid >> 4;
    const int row0 = blockIdx.y * 64, col0 = blockIdx.x * 64;
    float acc[4][4];
#pragma unroll
    for (int i = 0; i < 4; i++)
#pragma unroll
        for (int j = 0; j < 4; j++) acc[i][j] = 0.f;

    const int ar = tid >> 2, ak = (tid & 3) * 4;
    const int kbeg = s * 512, kend = kbeg + 512;

    for (int k0 = kbeg; k0 < kend; k0 += 16) {
        {
            float4 v = make_float4(0.f,0.f,0.f,0.f);
            int arow = row0 + ar;
            if (arow < DIM) v = *(const float4*)(A + (size_t)arow * NNODE + k0 + ak);
            As[ak][ar] = v.x; As[ak+1][ar] = v.y; As[ak+2][ar] = v.z; As[ak+3][ar] = v.w;
        }
        {
            int bk = tid >> 4;
            int bc = (tid & 15) * 4;
            float v[4] = {0.f,0.f,0.f,0.f};
            const float* bp = B + (size_t)(k0 + bk) * WCATC + col0 + bc;
#pragma unroll
            for (int q = 0; q < 4; q++) { if (col0 + bc + q < DIM) v[q] = bp[q]; }
#pragma unroll
            for (int q = 0; q < 4; q++) Bs[bk][bc + q] = v[q];
        }
        __syncthreads();
#pragma unroll
        for (int kk = 0; kk < 16; kk++) {
            float a[4], b[4];
#pragma unroll
            for (int i = 0; i < 4; i++) a[i] = As[kk][ty*4 + i];
#pragma unroll
            for (int j = 0; j < 4; j++) b[j] = Bs[kk][tx*4 + j];
#pragma unroll
            for (int i = 0; i < 4; i++)
#pragma unroll
                for (int j = 0; j < 4; j++) acc[i][j] += a[i] * b[j];
        }
        __syncthreads();
    }
#pragma unroll
    for (int i = 0; i < 4; i++) {
        int row = row0 + ty*4 + i;
        if (row >= DIM) continue;
#pragma unroll
        for (int j = 0; j < 4; j++) {
            int col = col0 + tx*4 + j;
            if (col >= DIM) continue;
            C[(size_t)row * DIM + col] = acc[i][j];
        }
    }
}

__global__ void reduce_g(const float* __restrict__ Gpart, float* __restrict__ G) {
    int idx = blockIdx.x * blockDim.x + threadIdx.x;
    if (idx >= 3*GDIM) return;
    int g = idx / GDIM, ij = idx % GDIM;
    float s = 0.f;
#pragma unroll
    for (int k = 0; k < 8; k++) s += Gpart[(size_t)(g*8 + k) * GDIM + ij];
    G[idx] = s;
}

// ---------------- sparse S = adj @ Wcat (one warp per row, ballot compaction) ----
// Deterministic: nonzeros processed in ascending column order within each warp.
__global__ void spmm(const float* __restrict__ adj, const float* __restrict__ Wcat,
                     float* __restrict__ S)
{
    int warp = (blockIdx.x * blockDim.x + threadIdx.x) >> 5;
    int lane = threadIdx.x & 31;
    if (warp >= NNODE) return;
    const float* arow = adj + (size_t)warp * NNODE;

    float acc[19];
#pragma unroll
    for (int c = 0; c < 19; c++) acc[c] = 0.f;

    for (int base = 0; base < NNODE; base += 32) {
        float v = arow[base + lane];
        unsigned m = __ballot_sync(0xffffffffu, v != 0.f);
        while (m) {
            int b = __ffs(m) - 1;
            m &= m - 1;
            float val = __shfl_sync(0xffffffffu, v, b);
            const float* wrow = Wcat + (size_t)(base + b) * WCATC;
#pragma unroll
            for (int c = 0; c < 18; c++) acc[c] += val * wrow[lane + 32*c];
            if (lane < WCATC - 18*32) acc[18] += val * wrow[lane + 18*32];
        }
    }
    float* srow = S + (size_t)warp * WCATC;
#pragma unroll
    for (int c = 0; c < 18; c++) srow[lane + 32*c] = acc[c];
    if (lane < WCATC - 18*32) srow[lane + 18*32] = acc[18];
}

// ---------------- GRU pointwise ----------------
__device__ __forceinline__ float sigm(float x) { return 1.f / (1.f + __expf(-x)); }

__global__ void pointwise1(const float* __restrict__ G, const float* __restrict__ br,
                           const float* __restrict__ bu, const float* __restrict__ A12,
                           const float* __restrict__ wv, float* __restrict__ rw,
                           float* __restrict__ ub)
{
    int idx = blockIdx.x * blockDim.x + threadIdx.x;
    if (idx >= WVSZ) return;
    int m = idx / DIM;          // 0..1599
    int j = idx % DIM;
    int ij = idx % GDIM;
    float r = sigm(G[ij] + br[ij] + A12[(size_t)m * (2*DIM) + j]);
    float u = sigm(G[GDIM + ij] + bu[ij] + A12[(size_t)m * (2*DIM) + DIM + j]);
    rw[idx] = r * wv[idx];
    ub[idx] = u;
}

__global__ void pointwise2(const float* __restrict__ G, const float* __restrict__ bh,
                           const float* __restrict__ A3, const float* __restrict__ ub,
                           float* __restrict__ wv)
{
    int idx = blockIdx.x * blockDim.x + threadIdx.x;
    if (idx >= WVSZ) return;
    int ij = idx % GDIM;
    float hc = tanhf(G[2*GDIM + ij] + bh[ij] + A3[idx]);
    float u = ub[idx];
    float w = wv[idx];
    wv[idx] = (1.f - u) * w + u * hc;
}

// ---------------- softmax over memory-reinterpreted GAT output ----------------
// embeds[t,n,o] = softmax_o( O[t*819200 + o*4096 + n] )
__global__ void softmax_k(const float* __restrict__ O, float* __restrict__ out)
{
    __shared__ float sm[256];
    int n = blockIdx.x, t = blockIdx.y;
    int tid = threadIdx.x;
    const float* base = O + (size_t)t * NNODE * DIM;
    float v = (tid < DIM) ? base[(size_t)tid * NNODE + n] : -1e30f;
    sm[tid] = v;
    __syncthreads();
#pragma unroll
    for (int st = 128; st > 0; st >>= 1) {
        if (tid < st) sm[tid] = fmaxf(sm[tid], sm[tid + st]);
        __syncthreads();
    }
    float mx = sm[0];
    __syncthreads();
    float e = (tid < DIM) ? __expf(v - mx) : 0.f;
    sm[tid] = e;
    __syncthreads();
#pragma unroll
    for (int st = 128; st > 0; st >>= 1) {
        if (tid < st) sm[tid] += sm[tid + st];
        __syncthreads();
    }
    float s = sm[0];
    if (tid < DIM)
        out[(size_t)t * NNODE * DIM + (size_t)n * DIM + tid] = e / s;
}

// ---------------- host driver ----------------
extern "C" void kernel_launch(void* const* d_in, const int* in_sizes, int n_in,
                              void* d_out, int out_size)
{
    const float* adjs    = (const float*)d_in[0];
    const float* feats   = (const float*)d_in[1];
    const float* init_wv = (const float*)d_in[3];
    const float* W1 = (const float*)d_in[4];
    const float* b1 = (const float*)d_in[5];
    const float* W2 = (const float*)d_in[10];
    const float* b2 = (const float*)d_in[11];
    const float* Wr = (const float*)d_in[16];
    const float* Ur = (const float*)d_in[17];
    const float* Pr = (const float*)d_in[18];
    const float* br = (const float*)d_in[19];
    const float* Wu = (const float*)d_in[20];
    const float* Uu = (const float*)d_in[21];
    const float* Pu = (const float*)d_in[22];
    const float* bu = (const float*)d_in[23];
    const float* Wh = (const float*)d_in[24];
    const float* Uh = (const float*)d_in[25];
    const float* Ph = (const float*)d_in[26];
    const float* bh = (const float*)d_in[27];

    float *W2eff, *Wcat, *Ucat, *H, *O, *S, *G, *Gpart, *wv, *A12, *A3, *rw, *ub;
    cudaGetSymbolAddress((void**)&W2eff, g_W2eff);
    cudaGetSymbolAddress((void**)&Wcat,  g_Wcat);
    cudaGetSymbolAddress((void**)&Ucat,  g_Ucat);
    cudaGetSymbolAddress((void**)&H,     g_H);
    cudaGetSymbolAddress((void**)&O,     g_O);
    cudaGetSymbolAddress((void**)&S,     g_S);
    cudaGetSymbolAddress((void**)&G,     g_G);
    cudaGetSymbolAddress((void**)&Gpart, g_Gpart);
    cudaGetSymbolAddress((void**)&wv,    g_wv);
    cudaGetSymbolAddress((void**)&A12,   g_A12);
    cudaGetSymbolAddress((void**)&A3,    g_A3);
    cudaGetSymbolAddress((void**)&rw,    g_rw);
    cudaGetSymbolAddress((void**)&ub,    g_ub);

    float* out = (float*)d_out;

    // ---- setup ----
    build_w2eff<<<(GDIM + 255)/256, 256>>>(W2, W2eff);
    build_wcat <<<(NNODE*DIM + 255)/256, 256>>>(Wr, Wu, Wh, Wcat);
    build_ucat <<<(GDIM + 255)/256, 256>>>(Ur, Uu, Ucat);
    copyk      <<<(WVSZ + 255)/256, 256>>>(wv, init_wv, WVSZ);

    // ---- GAT (all 4 timesteps batched as M=16384) ----
    dim3 gg((DIM + 63)/64, MBATCH/64);   // (4, 256)
    sgemm64<true,  true><<<gg, 256>>>(feats, DIM, W1,    DIM, b1, H, DIM, MBATCH, DIM, DIM);
    sgemm64<true,  true><<<gg, 256>>>(H,     DIM, W2eff, DIM, b2, O, DIM, MBATCH, DIM, DIM);
    softmax_k<<<dim3(NNODE, TT), 256>>>(O, out);

    // ---- GRU scan over adjs[1..3] ----
    for (int t = 1; t < TT; t++) {
        const float* adj = adjs + (size_t)t * NNODE * NNODE;
        spmm<<<NNODE/8, 256>>>(adj, Wcat, S);
        sgemm_ps<<<dim3(4, 4, 24), 256>>>(Pr, Pu, Ph, S, Gpart);
        reduce_g<<<(3*GDIM + 255)/256, 256>>>(Gpart, G);

        // A12 = wv[1600,200] @ Ucat[200,400]
        sgemm64<false, false><<<dim3(7, 25), 256>>>(wv, DIM, Ucat, 2*DIM, nullptr,
                                                    A12, 2*DIM, HEADS*DIM, 2*DIM, DIM);
        pointwise1<<<(WVSZ + 255)/256, 256>>>(G, br, bu, A12, wv, rw, ub);
        // A3 = rw[1600,200] @ Uh[200,200]
        sgemm64<false, false><<<dim3(4, 25), 256>>>(rw, DIM, Uh, DIM, nullptr,
                                                    A3, DIM, HEADS*DIM, DIM, DIM);
        pointwise2<<<(WVSZ + 255)/256, 256>>>(G, bh, A3, ub, wv);
    }

    // ---- final_wv after embeds ----
    copyk<<<(WVSZ + 255)/256, 256>>>(out + (size_t)TT * NNODE * DIM, wv, WVSZ);
}

// round 9
// speedup vs baseline: 1.0106x; 1.0106x over previous
#include <cuda_runtime.h>
#include <math.h>

#define NNODE 4096
#define DIM   200
#define TT    4
#define HEADS 8
#define GDIM  (DIM*DIM)          // 40000
#define MBATCH (TT*NNODE)        // 16384
#define WVSZ  (HEADS*DIM*DIM)    // 320000
#define WCATC 600                // 3*DIM

// ---------------- scratch (device globals; no allocation allowed) ----------------
__device__ float g_W2eff[GDIM];
__device__ float g_Wcat[NNODE*WCATC];
__device__ float g_Ucat[DIM*2*DIM];
__device__ float g_H[MBATCH*DIM];
__device__ float g_O[MBATCH*DIM];
__device__ float g_S[NNODE*WCATC];
__device__ float g_G[3*GDIM];
__device__ float g_Gpart[24*GDIM];
__device__ float g_wv[WVSZ];
__device__ float g_A12[HEADS*DIM*2*DIM];
__device__ float g_A3[WVSZ];
__device__ float g_rw[WVSZ];
__device__ float g_ub[WVSZ];

// ---------------- small helpers ----------------
__global__ void copyk(float* __restrict__ dst, const float* __restrict__ src, int n) {
    int i = blockIdx.x * blockDim.x + threadIdx.x;
    if (i < n) dst[i] = src[i];
}

__global__ void build_w2eff(const float* __restrict__ W2, float* __restrict__ out) {
    int idx = blockIdx.x * blockDim.x + threadIdx.x;
    if (idx >= GDIM) return;
    int o = idx / DIM, j = idx % DIM;
    float s = 0.f;
#pragma unroll
    for (int k = 0; k < HEADS; k++) s += W2[(size_t)o * (HEADS*DIM) + k*DIM + j];
    out[idx] = s;
}

__global__ void build_wcat(const float* __restrict__ Wr, const float* __restrict__ Wu,
                           const float* __restrict__ Wh, float* __restrict__ out) {
    int idx = blockIdx.x * blockDim.x + threadIdx.x;
    if (idx >= NNODE*DIM) return;
    int k = idx / DIM, j = idx % DIM;
    out[(size_t)k*WCATC + j]        = Wr[idx];
    out[(size_t)k*WCATC + DIM + j]  = Wu[idx];
    out[(size_t)k*WCATC + 2*DIM + j]= Wh[idx];
}

__global__ void build_ucat(const float* __restrict__ Ur, const float* __restrict__ Uu,
                           float* __restrict__ out) {
    int idx = blockIdx.x * blockDim.x + threadIdx.x;
    if (idx >= GDIM) return;
    int k = idx / DIM, j = idx % DIM;
    out[(size_t)k*(2*DIM) + j]       = Ur[idx];
    out[(size_t)k*(2*DIM) + DIM + j] = Uu[idx];
}

// ---------------- generic tiled SGEMM: C = A @ op(B) (+bias, elu) ----------------
// 64x64 tile, BK=16, 256 threads, 4x4 micro-tile.
// TRANSB: B stored [N,K] (ldb = row stride), op(B)=B^T. else B stored [K,N].
template<bool TRANSB, bool BIAS_ELU>
__global__ void sgemm64(const float* __restrict__ A, int lda,
                        const float* __restrict__ B, int ldb,
                        const float* __restrict__ bias,
                        float* __restrict__ C, int ldc,
                        int M, int N, int K)
{
    __shared__ float As[16][64];
    __shared__ float Bs[16][64];
    const int tid = threadIdx.x;
    const int tx = tid & 15, ty = tid >> 4;
    const int row0 = blockIdx.y * 64, col0 = blockIdx.x * 64;
    float acc[4][4];
#pragma unroll
    for (int i = 0; i < 4; i++)
#pragma unroll
        for (int j = 0; j < 4; j++) acc[i][j] = 0.f;

    const int ar = tid >> 2;          // 0..63
    const int ak = (tid & 3) * 4;     // 0,4,8,12

    for (int k0 = 0; k0 < K; k0 += 16) {
        // A tile -> As[k][row]
        {
            float v[4] = {0.f,0.f,0.f,0.f};
            int arow = row0 + ar;
            if (arow < M) {
                const float* ap = A + (size_t)arow * lda + k0 + ak;
#pragma unroll
                for (int q = 0; q < 4; q++) { if (k0 + ak + q < K) v[q] = ap[q]; }
            }
#pragma unroll
            for (int q = 0; q < 4; q++) As[ak + q][ar] = v[q];
        }
        // B tile -> Bs[k][col]
        if (!TRANSB) {
            int bk = tid >> 4;          // 0..15
            int bc = (tid & 15) * 4;    // 0..60
            float v[4] = {0.f,0.f,0.f,0.f};
            if (k0 + bk < K) {
                const float* bp = B + (size_t)(k0 + bk) * ldb + col0 + bc;
#pragma unroll
                for (int q = 0; q < 4; q++) { if (col0 + bc + q < N) v[q] = bp[q]; }
            }
#pragma unroll
            for (int q = 0; q < 4; q++) Bs[bk][bc + q] = v[q];
        } else {
            int bn = tid >> 2;          // 0..63 (output col)
            int bk = (tid & 3) * 4;
            float v[4] = {0.f,0.f,0.f,0.f};
            if (col0 + bn < N) {
                const float* bp = B + (size_t)(col0 + bn) * ldb + k0 + bk;
#pragma unroll
                for (int q = 0; q < 4; q++) { if (k0 + bk + q < K) v[q] = bp[q]; }
            }
#pragma unroll
            for (int q = 0; q < 4; q++) Bs[bk + q][bn] = v[q];
        }
        __syncthreads();
#pragma unroll
        for (int kk = 0; kk < 16; kk++) {
            float a[4], b[4];
#pragma unroll
            for (int i = 0; i < 4; i++) a[i] = As[kk][ty*4 + i];
#pragma unroll
            for (int j = 0; j < 4; j++) b[j] = Bs[kk][tx*4 + j];
#pragma unroll
            for (int i = 0; i < 4; i++)
#pragma unroll
                for (int j = 0; j < 4; j++) acc[i][j] += a[i] * b[j];
        }
        __syncthreads();
    }

#pragma unroll
    for (int i = 0; i < 4; i++) {
        int row = row0 + ty*4 + i;
        if (row >= M) continue;
#pragma unroll
        for (int j = 0; j < 4; j++) {
            int col = col0 + tx*4 + j;
            if (col >= N) continue;
            float v = acc[i][j];
            if (BIAS_ELU) { v += bias[col]; v = v > 0.f ? v : expm1f(v); }
            C[(size_t)row * ldc + col] = v;
        }
    }
}

// ---------------- split-K batched GEMM for G_g = P_g @ S[:, g*200:(g+1)*200] ----
// grid (4, 4, 24): z -> gate g = z>>3, k-chunk s = z&7 (K chunks of 512).
// Writes deterministic partials; reduce_g sums them in fixed order.
__global__ void sgemm_ps(const float* __restrict__ Pr, const float* __restrict__ Pu,
                         const float* __restrict__ Ph, const float* __restrict__ S,
                         float* __restrict__ Gpart)
{
    __shared__ float As[16][64];
    __shared__ float Bs[16][64];
    const int z = blockIdx.z, g = z >> 3, s = z & 7;
    const float* A = (g == 0) ? Pr : ((g == 1) ? Pu : Ph);   // [200, 4096]
    const float* B = S + g * DIM;                            // ldb = 600
    float* C = Gpart + (size_t)z * GDIM;

    const int tid = threadIdx.x;
    const int tx = tid & 15, ty = tid >> 4;
    const int row0 = blockIdx.y * 64, col0 = blockIdx.x * 64;
    float acc[4][4];
#pragma unroll
    for (int i = 0; i < 4; i++)
#pragma unroll
        for (int j = 0; j < 4; j++) acc[i][j] = 0.f;

    const int ar = tid >> 2, ak = (tid & 3) * 4;
    const int kbeg = s * 512, kend = kbeg + 512;

    for (int k0 = kbeg; k0 < kend; k0 += 16) {
        {
            float4 v = make_float4(0.f,0.f,0.f,0.f);
            int arow = row0 + ar;
            if (arow < DIM) v = *(const float4*)(A + (size_t)arow * NNODE + k0 + ak);
            As[ak][ar] = v.x; As[ak+1][ar] = v.y; As[ak+2][ar] = v.z; As[ak+3][ar] = v.w;
        }
        {
            int bk = tid >> 4;
            int bc = (tid & 15) * 4;
            float v[4] = {0.f,0.f,0.f,0.f};
            const float* bp = B + (size_t)(k0 + bk) * WCATC + col0 + bc;
#pragma unroll
            for (int q = 0; q < 4; q++) { if (col0 + bc + q < DIM) v[q] = bp[q]; }
#pragma unroll
            for (int q = 0; q < 4; q++) Bs[bk][bc + q] = v[q];
        }
        __syncthreads();
#pragma unroll
        for (int kk = 0; kk < 16; kk++) {
            float a[4], b[4];
#pragma unroll
            for (int i = 0; i < 4; i++) a[i] = As[kk][ty*4 + i];
#pragma unroll
            for (int j = 0; j < 4; j++) b[j] = Bs[kk][tx*4 + j];
#pragma unroll
            for (int i = 0; i < 4; i++)
#pragma unroll
                for (int j = 0; j < 4; j++) acc[i][j] += a[i] * b[j];
        }
        __syncthreads();
    }
#pragma unroll
    for (int i = 0; i < 4; i++) {
        int row = row0 + ty*4 + i;
        if (row >= DIM) continue;
#pragma unroll
        for (int j = 0; j < 4; j++) {
            int col = col0 + tx*4 + j;
            if (col >= DIM) continue;
            C[(size_t)row * DIM + col] = acc[i][j];
        }
    }
}

__global__ void reduce_g(const float* __restrict__ Gpart, float* __restrict__ G) {
    int idx = blockIdx.x * blockDim.x + threadIdx.x;
    if (idx >= 3*GDIM) return;
    int g = idx / GDIM, ij = idx % GDIM;
    float s = 0.f;
#pragma unroll
    for (int k = 0; k < 8; k++) s += Gpart[(size_t)(g*8 + k) * GDIM + ij];
    G[idx] = s;
}

// ---------------- sparse S = adj @ Wcat (one warp per row, ballot compaction) ----
// Deterministic: nonzeros processed in ascending column order within each warp.
__global__ void spmm(const float* __restrict__ adj, const float* __restrict__ Wcat,
                     float* __restrict__ S)
{
    int warp = (blockIdx.x * blockDim.x + threadIdx.x) >> 5;
    int lane = threadIdx.x & 31;
    if (warp >= NNODE) return;
    const float* arow = adj + (size_t)warp * NNODE;

    float acc[19];
#pragma unroll
    for (int c = 0; c < 19; c++) acc[c] = 0.f;

    for (int base = 0; base < NNODE; base += 32) {
        float v = arow[base + lane];
        unsigned m = __ballot_sync(0xffffffffu, v != 0.f);
        while (m) {
            int b = __ffs(m) - 1;
            m &= m - 1;
            float val = __shfl_sync(0xffffffffu, v, b);
            const float* wrow = Wcat + (size_t)(base + b) * WCATC;
#pragma unroll
            for (int c = 0; c < 18; c++) acc[c] += val * wrow[lane + 32*c];
            if (lane < WCATC - 18*32) acc[18] += val * wrow[lane + 18*32];
        }
    }
    float* srow = S + (size_t)warp * WCATC;
#pragma unroll
    for (int c = 0; c < 18; c++) srow[lane + 32*c] = acc[c];
    if (lane < WCATC - 18*32) srow[lane + 18*32] = acc[18];
}

// ---------------- GRU pointwise ----------------
__device__ __forceinline__ float sigm(float x) { return 1.f / (1.f + __expf(-x)); }

__global__ void pointwise1(const float* __restrict__ G, const float* __restrict__ br,
                           const float* __restrict__ bu, const float* __restrict__ A12,
                           const float* __restrict__ wv, float* __restrict__ rw,
                           float* __restrict__ ub)
{
    int idx = blockIdx.x * blockDim.x + threadIdx.x;
    if (idx >= WVSZ) return;
    int m = idx / DIM;          // 0..1599
    int j = idx % DIM;
    int ij = idx % GDIM;
    float r = sigm(G[ij] + br[ij] + A12[(size_t)m * (2*DIM) + j]);
    float u = sigm(G[GDIM + ij] + bu[ij] + A12[(size_t)m * (2*DIM) + DIM + j]);
    rw[idx] = r * wv[idx];
    ub[idx] = u;
}

__global__ void pointwise2(const float* __restrict__ G, const float* __restrict__ bh,
                           const float* __restrict__ A3, const float* __restrict__ ub,
                           float* __restrict__ wv)
{
    int idx = blockIdx.x * blockDim.x + threadIdx.x;
    if (idx >= WVSZ) return;
    int ij = idx % GDIM;
    float hc = tanhf(G[2*GDIM + ij] + bh[ij] + A3[idx]);
    float u = ub[idx];
    float w = wv[idx];
    wv[idx] = (1.f - u) * w + u * hc;
}

// ---------------- softmax over memory-reinterpreted GAT output ----------------
// embeds[t,n,o] = softmax_o( O[t*819200 + o*4096 + n] )
__global__ void softmax_k(const float* __restrict__ O, float* __restrict__ out)
{
    __shared__ float sm[256];
    int n = blockIdx.x, t = blockIdx.y;
    int tid = threadIdx.x;
    const float* base = O + (size_t)t * NNODE * DIM;
    float v = (tid < DIM) ? base[(size_t)tid * NNODE + n] : -1e30f;
    sm[tid] = v;
    __syncthreads();
#pragma unroll
    for (int st = 128; st > 0; st >>= 1) {
        if (tid < st) sm[tid] = fmaxf(sm[tid], sm[tid + st]);
        __syncthreads();
    }
    float mx = sm[0];
    __syncthreads();
    float e = (tid < DIM) ? __expf(v - mx) : 0.f;
    sm[tid] = e;
    __syncthreads();
#pragma unroll
    for (int st = 128; st > 0; st >>= 1) {
        if (tid < st) sm[tid] += sm[tid + st];
        __syncthreads();
    }
    float s = sm[0];
    if (tid < DIM)
        out[(size_t)t * NNODE * DIM + (size_t)n * DIM + tid] = e / s;
}

// ---------------- host driver ----------------
extern "C" void kernel_launch(void* const* d_in, const int* in_sizes, int n_in,
                              void* d_out, int out_size)
{
    const float* adjs    = (const float*)d_in[0];
    const float* feats   = (const float*)d_in[1];
    const float* init_wv = (const float*)d_in[3];
    const float* W1 = (const float*)d_in[4];
    const float* b1 = (const float*)d_in[5];
    const float* W2 = (const float*)d_in[10];
    const float* b2 = (const float*)d_in[11];
    const float* Wr = (const float*)d_in[16];
    const float* Ur = (const float*)d_in[17];
    const float* Pr = (const float*)d_in[18];
    const float* br = (const float*)d_in[19];
    const float* Wu = (const float*)d_in[20];
    const float* Uu = (const float*)d_in[21];
    const float* Pu = (const float*)d_in[22];
    const float* bu = (const float*)d_in[23];
    const float* Wh = (const float*)d_in[24];
    const float* Uh = (const float*)d_in[25];
    const float* Ph = (const float*)d_in[26];
    const float* bh = (const float*)d_in[27];

    float *W2eff, *Wcat, *Ucat, *H, *O, *S, *G, *Gpart, *wv, *A12, *A3, *rw, *ub;
    cudaGetSymbolAddress((void**)&W2eff, g_W2eff);
    cudaGetSymbolAddress((void**)&Wcat,  g_Wcat);
    cudaGetSymbolAddress((void**)&Ucat,  g_Ucat);
    cudaGetSymbolAddress((void**)&H,     g_H);
    cudaGetSymbolAddress((void**)&O,     g_O);
    cudaGetSymbolAddress((void**)&S,     g_S);
    cudaGetSymbolAddress((void**)&G,     g_G);
    cudaGetSymbolAddress((void**)&Gpart, g_Gpart);
    cudaGetSymbolAddress((void**)&wv,    g_wv);
    cudaGetSymbolAddress((void**)&A12,   g_A12);
    cudaGetSymbolAddress((void**)&A3,    g_A3);
    cudaGetSymbolAddress((void**)&rw,    g_rw);
    cudaGetSymbolAddress((void**)&ub,    g_ub);

    float* out = (float*)d_out;

    // ---- setup ----
    build_w2eff<<<(GDIM + 255)/256, 256>>>(W2, W2eff);
    build_wcat <<<(NNODE*DIM + 255)/256, 256>>>(Wr, Wu, Wh, Wcat);
    build_ucat <<<(GDIM + 255)/256, 256>>>(Ur, Uu, Ucat);
    copyk      <<<(WVSZ + 255)/256, 256>>>(wv, init_wv, WVSZ);

    // ---- GAT (all 4 timesteps batched as M=16384) ----
    dim3 gg((DIM + 63)/64, MBATCH/64);   // (4, 256)
    sgemm64<true,  true><<<gg, 256>>>(feats, DIM, W1,    DIM, b1, H, DIM, MBATCH, DIM, DIM);
    sgemm64<true,  true><<<gg, 256>>>(H,     DIM, W2eff, DIM, b2, O, DIM, MBATCH, DIM, DIM);
    softmax_k<<<dim3(NNODE, TT), 256>>>(O, out);

    // ---- GRU scan over adjs[1..3] ----
    for (int t = 1; t < TT; t++) {
        const float* adj = adjs + (size_t)t * NNODE * NNODE;
        spmm<<<NNODE/8, 256>>>(adj, Wcat, S);
        sgemm_ps<<<dim3(4, 4, 24), 256>>>(Pr, Pu, Ph, S, Gpart);
        reduce_g<<<(3*GDIM + 255)/256, 256>>>(Gpart, G);

        // A12 = wv[1600,200] @ Ucat[200,400]
        sgemm64<false, false><<<dim3(7, 25), 256>>>(wv, DIM, Ucat, 2*DIM, nullptr,
                                                    A12, 2*DIM, HEADS*DIM, 2*DIM, DIM);
        pointwise1<<<(WVSZ + 255)/256, 256>>>(G, br, bu, A12, wv, rw, ub);
        // A3 = rw[1600,200] @ Uh[200,200]
        sgemm64<false, false><<<dim3(4, 25), 256>>>(rw, DIM, Uh, DIM, nullptr,
                                                    A3, DIM, HEADS*DIM, DIM, DIM);
        pointwise2<<<(WVSZ + 255)/256, 256>>>(G, bh, A3, ub, wv);
    }

    // ---- final_wv after embeds ----
    copyk<<<(WVSZ + 255)/256, 256>>>(out + (size_t)TT * NNODE * DIM, wv, WVSZ);
}